// round 3
// baseline (speedup 1.0000x reference)
#include <cuda_runtime.h>
#include <cstdint>

// Problem constants (fixed by the dataset)
#define N_NODES 100000
#define R_REL   32
#define E_EDGES 3200000
#define F_INF   128
#define H_DIM   16
#define C_CLS   8
#define COLS1   (R_REL * H_DIM)   // 512
#define COLS2   (R_REL * C_CLS)   // 256

// ---------------- scratch (device globals: allocation-free contract) --------
__device__ float g_xw1[(size_t)N_NODES * COLS1];   // 204.8 MB  [n][r*16+h]
__device__ float g_xw2[(size_t)N_NODES * COLS2];   // 102.4 MB  [n][r*8+c]
__device__ float g_h1[(size_t)N_NODES * H_DIM];    // 6.4 MB
__device__ float g_acc2[(size_t)N_NODES * C_CLS];  // 3.2 MB
__device__ int   g_deg[(size_t)N_NODES * R_REL];   // 12.8 MB
__device__ float g_norm[E_EDGES];                  // 12.8 MB
__device__ int   g_src[E_EDGES];
__device__ int   g_dst[E_EDGES];
__device__ int   g_typ[E_EDGES];
__device__ float g_Wc1[F_INF * COLS1];             // [f][r*16+h]
__device__ float g_Wc2[H_DIM * COLS2];             // [k][r*8+c]
__device__ int   g_is64;                            // edge dtype flag

// ---------------- small helpers --------------------------------------------
__device__ __forceinline__ unsigned long long fma2(unsigned long long a,
                                                   unsigned long long b,
                                                   unsigned long long c) {
    unsigned long long d;
    asm("fma.rn.f32x2 %0, %1, %2, %3;" : "=l"(d) : "l"(a), "l"(b), "l"(c));
    return d;
}
__device__ __forceinline__ unsigned long long bcast2(float x) {
    unsigned long long r;
    asm("mov.b64 %0, {%1, %1};" : "=l"(r) : "f"(x));
    return r;
}
__device__ __forceinline__ float2 unpack2(unsigned long long v) {
    float2 r;
    asm("mov.b64 {%0, %1}, %2;" : "=f"(r.x), "=f"(r.y) : "l"(v));
    return r;
}
__device__ __forceinline__ void red_add_v4(float* p, float a, float b, float c, float d) {
    asm volatile("red.global.add.v4.f32 [%0], {%1, %2, %3, %4};"
                 :: "l"(p), "f"(a), "f"(b), "f"(c), "f"(d) : "memory");
}

// ---------------- kernels ---------------------------------------------------

// Detect edge dtype: if buffer is int64 (values < 2^31, non-negative), every
// odd int32 word of the first 2048 pairs is zero. For int32 edge_type data
// (values in [0,32)), 2048 consecutive odd-position words cannot all be zero.
__global__ void k_probe(const int* __restrict__ et32) {
    __shared__ int nz;
    if (threadIdx.x == 0) nz = 0;
    __syncthreads();
    for (int i = threadIdx.x; i < 2048; i += blockDim.x) {
        if (et32[2 * i + 1] != 0) atomicOr(&nz, 1);
    }
    __syncthreads();
    if (threadIdx.x == 0) g_is64 = (nz == 0) ? 1 : 0;
}

// Zero accumulators (must run every call: graph replays)
__global__ void k_zero() {
    int i = blockIdx.x * blockDim.x + threadIdx.x;
    int stride = gridDim.x * blockDim.x;
    for (int j = i; j < N_NODES * R_REL; j += stride) g_deg[j] = 0;
    for (int j = i; j < N_NODES * H_DIM; j += stride) g_h1[j] = 0.0f;
    for (int j = i; j < N_NODES * C_CLS; j += stride) g_acc2[j] = 0.0f;
}

// Decode edge data (int32 or int64 per flag) -> int32, count per-(dst,rel) deg
__global__ void k_prep(const int* __restrict__ ei32,
                       const int* __restrict__ et32, int E) {
    int e = blockIdx.x * blockDim.x + threadIdx.x;
    if (e >= E) return;
    int s, d, t;
    if (g_is64) {
        s = ei32[2 * (size_t)e];
        d = ei32[2 * ((size_t)E + e)];
        t = et32[2 * (size_t)e];
    } else {
        s = ei32[e];
        d = ei32[(size_t)E + e];
        t = et32[e];
    }
    g_src[e] = s;
    g_dst[e] = d;
    g_typ[e] = t;
    atomicAdd(&g_deg[d * R_REL + t], 1);
}

__global__ void k_norm(int E) {
    int e = blockIdx.x * blockDim.x + threadIdx.x;
    if (e >= E) return;
    float deg = (float)g_deg[g_dst[e] * R_REL + g_typ[e]];
    g_norm[e] = 1.0f / fmaxf(deg, 1.0f);
}

// Repack W1 [R,128,16] -> Wc1 [128, 512];  W2 [R,16,8] -> Wc2 [16, 256]
__global__ void k_wprep(const float* __restrict__ W1, const float* __restrict__ W2) {
    int idx = blockIdx.x * blockDim.x + threadIdx.x;
    if (idx < F_INF * COLS1) {
        int f = idx / COLS1, c = idx % COLS1;
        int r = c / H_DIM, h = c % H_DIM;
        g_Wc1[idx] = W1[((size_t)r * F_INF + f) * H_DIM + h];
    } else {
        int j = idx - F_INF * COLS1;
        if (j < H_DIM * COLS2) {
            int k = j / COLS2, c = j % COLS2;
            int r = c / C_CLS, cc = c % C_CLS;
            g_Wc2[j] = W2[((size_t)r * H_DIM + k) * C_CLS + cc];
        }
    }
}

// GEMM1: xw1[n][c] = sum_f emb[n][f] * Wc1[f][c]
// Block: 128 threads, 64 nodes, 512 cols in 8 chunks of 64.
// Thread: 8 nodes (4 f32x2 pairs) x 4 cols = 16 packed accumulators.
__global__ void k_gemm1(const float* __restrict__ emb, int nN) {
    extern __shared__ float smem[];
    float* embS = smem;             // [128][64]  embS[f][n_local]
    float* wS = smem + 128 * 64;    // [128][64]  wS[f][c_local]

    int tid = threadIdx.x;
    int nb = blockIdx.x * 64;

    // Load emb tile transposed: embS[f][nl] = emb[nb+nl][f]
    {
        int nl = tid >> 1;
        int half = tid & 1;
        int node = nb + nl;
        bool ok = node < nN;
        const float4* src =
            (const float4*)(emb + (size_t)node * F_INF) + half * 16;
        #pragma unroll
        for (int i = 0; i < 16; i++) {
            float4 v = ok ? src[i] : make_float4(0.f, 0.f, 0.f, 0.f);
            int f = half * 64 + i * 4;
            embS[(f + 0) * 64 + nl] = v.x;
            embS[(f + 1) * 64 + nl] = v.y;
            embS[(f + 2) * 64 + nl] = v.z;
            embS[(f + 3) * 64 + nl] = v.w;
        }
    }

    int cg = tid & 15;   // col group: 4 cols
    int ng = tid >> 4;   // node group: 8 nodes

    for (int chunk = 0; chunk < 8; chunk++) {
        int cc = chunk * 64;
        __syncthreads();  // wS safe to overwrite; embS ready (first iter)
        // Load wS: thread tid owns f-row tid
        {
            const float4* src = (const float4*)(g_Wc1 + (size_t)tid * COLS1 + cc);
            float4* dstp = (float4*)(wS + tid * 64);
            #pragma unroll
            for (int i = 0; i < 16; i++) dstp[i] = src[i];
        }
        __syncthreads();

        unsigned long long acc[4][4];
        #pragma unroll
        for (int j = 0; j < 4; j++)
            #pragma unroll
            for (int c = 0; c < 4; c++) acc[j][c] = 0ull;

        #pragma unroll 8
        for (int f = 0; f < 128; f++) {
            const unsigned long long* ep =
                (const unsigned long long*)(embS + f * 64 + ng * 8);
            unsigned long long a0 = ep[0], a1 = ep[1], a2 = ep[2], a3 = ep[3];
            float4 w = *(const float4*)(wS + f * 64 + cg * 4);
            unsigned long long b0 = bcast2(w.x), b1 = bcast2(w.y),
                               b2 = bcast2(w.z), b3 = bcast2(w.w);
            acc[0][0] = fma2(a0, b0, acc[0][0]);
            acc[0][1] = fma2(a0, b1, acc[0][1]);
            acc[0][2] = fma2(a0, b2, acc[0][2]);
            acc[0][3] = fma2(a0, b3, acc[0][3]);
            acc[1][0] = fma2(a1, b0, acc[1][0]);
            acc[1][1] = fma2(a1, b1, acc[1][1]);
            acc[1][2] = fma2(a1, b2, acc[1][2]);
            acc[1][3] = fma2(a1, b3, acc[1][3]);
            acc[2][0] = fma2(a2, b0, acc[2][0]);
            acc[2][1] = fma2(a2, b1, acc[2][1]);
            acc[2][2] = fma2(a2, b2, acc[2][2]);
            acc[2][3] = fma2(a2, b3, acc[2][3]);
            acc[3][0] = fma2(a3, b0, acc[3][0]);
            acc[3][1] = fma2(a3, b1, acc[3][1]);
            acc[3][2] = fma2(a3, b2, acc[3][2]);
            acc[3][3] = fma2(a3, b3, acc[3][3]);
        }

        #pragma unroll
        for (int j = 0; j < 4; j++) {
            int n0 = nb + ng * 8 + 2 * j;
            float2 v0 = unpack2(acc[j][0]);
            float2 v1 = unpack2(acc[j][1]);
            float2 v2 = unpack2(acc[j][2]);
            float2 v3 = unpack2(acc[j][3]);
            if (n0 < nN) {
                float4 o = make_float4(v0.x, v1.x, v2.x, v3.x);
                *(float4*)(g_xw1 + (size_t)n0 * COLS1 + cc + cg * 4) = o;
            }
            if (n0 + 1 < nN) {
                float4 o = make_float4(v0.y, v1.y, v2.y, v3.y);
                *(float4*)(g_xw1 + (size_t)(n0 + 1) * COLS1 + cc + cg * 4) = o;
            }
        }
    }
}

// Scatter layer 1: h1[dst] += norm * xw1[src, typ*16 : +16]
__global__ void k_scatter1(int E) {
    int e = blockIdx.x * blockDim.x + threadIdx.x;
    if (e >= E) return;
    int s = g_src[e], d = g_dst[e], t = g_typ[e];
    float nrm = g_norm[e];
    const float4* x = (const float4*)(g_xw1 + (size_t)s * COLS1 + t * H_DIM);
    float* out = g_h1 + (size_t)d * H_DIM;
    #pragma unroll
    for (int i = 0; i < 4; i++) {
        float4 v = x[i];
        red_add_v4(out + i * 4, v.x * nrm, v.y * nrm, v.z * nrm, v.w * nrm);
    }
}

// GEMM2 (relu fused): xw2[n][c] = sum_k relu(h1[n][k]) * Wc2[k][c]
// Thread = (node, 4 cols); 64 threads per node.
__global__ void k_gemm2(int nN) {
    int g = blockIdx.x * blockDim.x + threadIdx.x;
    if (g >= nN * 64) return;
    int n = g >> 6;
    int cg = g & 63;
    const float4* h4 = (const float4*)(g_h1 + (size_t)n * H_DIM);
    float hv[16];
    #pragma unroll
    for (int q = 0; q < 4; q++) {
        float4 h = h4[q];
        hv[q * 4 + 0] = fmaxf(h.x, 0.f);
        hv[q * 4 + 1] = fmaxf(h.y, 0.f);
        hv[q * 4 + 2] = fmaxf(h.z, 0.f);
        hv[q * 4 + 3] = fmaxf(h.w, 0.f);
    }
    float4 acc = make_float4(0.f, 0.f, 0.f, 0.f);
    #pragma unroll
    for (int k = 0; k < 16; k++) {
        float4 w = *(const float4*)(g_Wc2 + k * COLS2 + cg * 4);
        acc.x = fmaf(hv[k], w.x, acc.x);
        acc.y = fmaf(hv[k], w.y, acc.y);
        acc.z = fmaf(hv[k], w.z, acc.z);
        acc.w = fmaf(hv[k], w.w, acc.w);
    }
    *(float4*)(g_xw2 + (size_t)n * COLS2 + cg * 4) = acc;
}

// Scatter layer 2: acc2[dst] += norm * xw2[src, typ*8 : +8]
__global__ void k_scatter2(int E) {
    int e = blockIdx.x * blockDim.x + threadIdx.x;
    if (e >= E) return;
    int s = g_src[e], d = g_dst[e], t = g_typ[e];
    float nrm = g_norm[e];
    const float4* x = (const float4*)(g_xw2 + (size_t)s * COLS2 + t * C_CLS);
    float* out = g_acc2 + (size_t)d * C_CLS;
    float4 v0 = x[0], v1 = x[1];
    red_add_v4(out + 0, v0.x * nrm, v0.y * nrm, v0.z * nrm, v0.w * nrm);
    red_add_v4(out + 4, v1.x * nrm, v1.y * nrm, v1.z * nrm, v1.w * nrm);
}

// log_softmax over 8 classes per node
__global__ void k_softmax(int nN, float* __restrict__ out) {
    int n = blockIdx.x * blockDim.x + threadIdx.x;
    if (n >= nN) return;
    const float4* p = (const float4*)(g_acc2 + (size_t)n * C_CLS);
    float4 a = p[0], b = p[1];
    float m = fmaxf(fmaxf(fmaxf(a.x, a.y), fmaxf(a.z, a.w)),
                    fmaxf(fmaxf(b.x, b.y), fmaxf(b.z, b.w)));
    float s = expf(a.x - m) + expf(a.y - m) + expf(a.z - m) + expf(a.w - m) +
              expf(b.x - m) + expf(b.y - m) + expf(b.z - m) + expf(b.w - m);
    float l = m + logf(s);
    float4* o = (float4*)(out + (size_t)n * C_CLS);
    o[0] = make_float4(a.x - l, a.y - l, a.z - l, a.w - l);
    o[1] = make_float4(b.x - l, b.y - l, b.z - l, b.w - l);
}

// ---------------- launch ----------------------------------------------------
extern "C" void kernel_launch(void* const* d_in, const int* in_sizes, int n_in,
                              void* d_out, int out_size) {
    const float* emb = (const float*)d_in[0];
    const float* W1 = (const float*)d_in[1];
    const float* W2 = (const float*)d_in[2];
    const int* ei32 = (const int*)d_in[3];
    const int* et32 = (const int*)d_in[4];

    int E = in_sizes[4];
    int nN = in_sizes[0] / F_INF;

    k_probe<<<1, 256>>>(et32);
    k_zero<<<512, 256>>>();
    k_prep<<<(E + 255) / 256, 256>>>(ei32, et32, E);
    k_norm<<<(E + 255) / 256, 256>>>(E);
    k_wprep<<<(F_INF * COLS1 + H_DIM * COLS2 + 255) / 256, 256>>>(W1, W2);

    cudaFuncSetAttribute(k_gemm1, cudaFuncAttributeMaxDynamicSharedMemorySize,
                         65536);
    k_gemm1<<<(nN + 63) / 64, 128, 65536>>>(emb, nN);

    k_scatter1<<<(E + 255) / 256, 256>>>(E);
    k_gemm2<<<(nN * 64 + 255) / 256, 256>>>(nN);
    k_scatter2<<<(E + 255) / 256, 256>>>(E);
    k_softmax<<<(nN + 255) / 256, 256>>>(nN, (float*)d_out);
}